// round 2
// baseline (speedup 1.0000x reference)
#include <cuda_runtime.h>

namespace {
constexpr int kB  = 2;
constexpr int kH  = 8;
constexpr int kS  = 2048;
constexpr int kDK = 32;
constexpr int kDM = 256;
constexpr int kNRow = kB * kS;           // 4096
constexpr float kScale = 0.17677669529663687f;  // 1/sqrt(32)
}

// Scratch: projected Q/K/V in [b,h,s,d] layout (4 MB each). Static __device__
// arrays (no allocations allowed in kernel_launch).
__device__ float g_q[kB * kH * kS * kDK];
__device__ float g_k[kB * kH * kS * kDK];
__device__ float g_v[kB * kH * kS * kDK];

// ---------------------------------------------------------------------------
// Projection GEMM: out = X @ W^T + bias, written transposed to [b,h,s,d].
// Tile 128x64, 256 threads, 8x4 microtile, BK=16.
// ---------------------------------------------------------------------------
__global__ __launch_bounds__(256)
void proj_kernel(const float* __restrict__ xq, const float* __restrict__ xk,
                 const float* __restrict__ xv,
                 const float* __restrict__ wq, const float* __restrict__ bq,
                 const float* __restrict__ wk, const float* __restrict__ bk,
                 const float* __restrict__ wv, const float* __restrict__ bv)
{
    constexpr int PBM = 128, PBN = 64, PBK = 16;
    __shared__ float As[PBK][PBM];
    __shared__ float Bs[PBK][PBN];

    const int z = blockIdx.z;
    const float* __restrict__ X    = (z == 0) ? xq : (z == 1) ? xk : xv;
    const float* __restrict__ W    = (z == 0) ? wq : (z == 1) ? wk : wv;
    const float* __restrict__ bias = (z == 0) ? bq : (z == 1) ? bk : bv;
    float* __restrict__ out        = (z == 0) ? g_q : (z == 1) ? g_k : g_v;

    const int n0 = blockIdx.y * PBM;   // row tile (b*S+s)
    const int c0 = blockIdx.x * PBN;   // col tile (h*32+d)
    const int tid = threadIdx.x;
    const int tx = tid & 15;           // 16 cols of threads -> 4 outputs each
    const int ty = tid >> 4;           // 16 rows of threads -> 8 outputs each

    float acc[8][4];
    #pragma unroll
    for (int i = 0; i < 8; ++i)
        #pragma unroll
        for (int j = 0; j < 4; ++j) acc[i][j] = 0.0f;

    for (int k0 = 0; k0 < kDM; k0 += PBK) {
        // Load A tile: 128 rows x 16 k = 512 float4, 2 per thread
        #pragma unroll
        for (int r = 0; r < 2; ++r) {
            int f   = tid + r * 256;
            int row = f >> 2;
            int kk  = (f & 3) * 4;
            float4 v = *reinterpret_cast<const float4*>(X + (n0 + row) * kDM + k0 + kk);
            As[kk + 0][row] = v.x; As[kk + 1][row] = v.y;
            As[kk + 2][row] = v.z; As[kk + 3][row] = v.w;
        }
        {   // Load B tile: 64 cols x 16 k = 256 float4, 1 per thread
            int n  = tid >> 2;
            int kk = (tid & 3) * 4;
            float4 v = *reinterpret_cast<const float4*>(W + (c0 + n) * kDM + k0 + kk);
            Bs[kk + 0][n] = v.x; Bs[kk + 1][n] = v.y;
            Bs[kk + 2][n] = v.z; Bs[kk + 3][n] = v.w;
        }
        __syncthreads();

        #pragma unroll
        for (int k = 0; k < PBK; ++k) {
            float4 a0 = *reinterpret_cast<const float4*>(&As[k][ty * 8]);
            float4 a1 = *reinterpret_cast<const float4*>(&As[k][ty * 8 + 4]);
            float4 bb = *reinterpret_cast<const float4*>(&Bs[k][tx * 4]);
            float a[8] = {a0.x, a0.y, a0.z, a0.w, a1.x, a1.y, a1.z, a1.w};
            float b[4] = {bb.x, bb.y, bb.z, bb.w};
            #pragma unroll
            for (int i = 0; i < 8; ++i)
                #pragma unroll
                for (int j = 0; j < 4; ++j)
                    acc[i][j] = fmaf(a[i], b[j], acc[i][j]);
        }
        __syncthreads();
    }

    // Epilogue: add bias, write transposed to [b,h,s,d]
    #pragma unroll
    for (int i = 0; i < 8; ++i) {
        const int row = n0 + ty * 8 + i;
        const int bb  = row / kS;
        const int ss  = row % kS;
        #pragma unroll
        for (int j = 0; j < 4; ++j) {
            const int col = c0 + tx * 4 + j;
            const int h = col >> 5, d = col & 31;
            out[((bb * kH + h) * kS + ss) * kDK + d] = acc[i][j] + bias[col];
        }
    }
}

// ---------------------------------------------------------------------------
// Fused sparsemax attention: 1 warp = 1 query row (2048 scores in 64 regs/lane),
// 8 warps/CTA share K tiles in shared memory. Michelot fixpoint for tau,
// ballot/shfl sparse AV.
// ---------------------------------------------------------------------------
__global__ __launch_bounds__(256)
void attn_kernel(float* __restrict__ out)
{
    __shared__ float4 Ks4[8 * 128];   // [d4][j], XOR-swizzled

    const int bh   = blockIdx.y;
    const int warp = threadIdx.x >> 5;
    const int lane = threadIdx.x & 31;
    const int qi   = blockIdx.x * 8 + warp;

    const float* __restrict__ Qrow = g_q + (bh * kS + qi) * kDK;
    const float* __restrict__ Kbh  = g_k + bh * kS * kDK;
    const float* __restrict__ Vbh  = g_v + bh * kS * kDK;

    // Broadcast q row into registers (all lanes identical)
    float q[kDK];
    #pragma unroll
    for (int d4 = 0; d4 < 8; ++d4) {
        float4 v = __ldg(reinterpret_cast<const float4*>(Qrow) + d4);
        q[4 * d4 + 0] = v.x; q[4 * d4 + 1] = v.y;
        q[4 * d4 + 2] = v.z; q[4 * d4 + 3] = v.w;
    }

    float s[64];   // score j = (i>>2)*128 + (i&3)*32 + lane

    #pragma unroll
    for (int t = 0; t < 16; ++t) {
        // Cooperative K tile load: 128 rows x 8 float4, transposed + swizzled
        #pragma unroll
        for (int r = 0; r < 4; ++r) {
            int f  = threadIdx.x + r * 256;
            int j  = f >> 3;
            int d4 = f & 7;
            Ks4[d4 * 128 + (j ^ d4)] =
                *reinterpret_cast<const float4*>(Kbh + (t * 128 + j) * kDK + d4 * 4);
        }
        __syncthreads();

        #pragma unroll
        for (int k = 0; k < 4; ++k) {
            const int j = k * 32 + lane;
            float a0 = 0.f, a1 = 0.f, a2 = 0.f, a3 = 0.f;  // 4 parallel FMA chains
            #pragma unroll
            for (int dd = 0; dd < 8; dd += 4) {
                float4 kv0 = Ks4[(dd + 0) * 128 + (j ^ (dd + 0))];
                float4 kv1 = Ks4[(dd + 1) * 128 + (j ^ (dd + 1))];
                float4 kv2 = Ks4[(dd + 2) * 128 + (j ^ (dd + 2))];
                float4 kv3 = Ks4[(dd + 3) * 128 + (j ^ (dd + 3))];
                a0 = fmaf(kv0.x, q[4*dd + 0], a0);  a0 = fmaf(kv0.y, q[4*dd + 1], a0);
                a0 = fmaf(kv0.z, q[4*dd + 2], a0);  a0 = fmaf(kv0.w, q[4*dd + 3], a0);
                a1 = fmaf(kv1.x, q[4*dd + 4], a1);  a1 = fmaf(kv1.y, q[4*dd + 5], a1);
                a1 = fmaf(kv1.z, q[4*dd + 6], a1);  a1 = fmaf(kv1.w, q[4*dd + 7], a1);
                a2 = fmaf(kv2.x, q[4*dd + 8], a2);  a2 = fmaf(kv2.y, q[4*dd + 9], a2);
                a2 = fmaf(kv2.z, q[4*dd +10], a2);  a2 = fmaf(kv2.w, q[4*dd +11], a2);
                a3 = fmaf(kv3.x, q[4*dd +12], a3);  a3 = fmaf(kv3.y, q[4*dd +13], a3);
                a3 = fmaf(kv3.z, q[4*dd +14], a3);  a3 = fmaf(kv3.w, q[4*dd +15], a3);
            }
            s[t * 4 + k] = (a0 + a1) + (a2 + a3);
        }
        __syncthreads();
    }

    #pragma unroll
    for (int i = 0; i < 64; ++i) s[i] *= kScale;

    // Row max (warp-wide over all 2048 scores)
    float m = -3.4e38f;
    #pragma unroll
    for (int i = 0; i < 64; ++i) m = fmaxf(m, s[i]);
    #pragma unroll
    for (int o = 16; o; o >>= 1)
        m = fmaxf(m, __shfl_xor_sync(0xffffffffu, m, o));

    // Michelot fixpoint: tau monotone non-decreasing, support strictly
    // shrinking -> exact sparsemax tau at termination.
    float tau = m - 1.0f;
    int prev = -1;
    for (int it = 0; it < 4096; ++it) {
        float sum = 0.0f;
        int cnt = 0;
        #pragma unroll
        for (int i = 0; i < 64; ++i) {
            if (s[i] > tau) { sum += s[i]; ++cnt; }
        }
        #pragma unroll
        for (int o = 16; o; o >>= 1) {
            sum += __shfl_xor_sync(0xffffffffu, sum, o);
            cnt += __shfl_xor_sync(0xffffffffu, cnt, o);
        }
        if (cnt == prev || cnt == 0) break;
        tau = (sum - 1.0f) / (float)cnt;
        prev = cnt;
    }

    // Sparse AV: lane owns output dim d = lane. Iterate nonzero weights only.
    float acc = 0.0f;
    #pragma unroll
    for (int i = 0; i < 64; ++i) {
        float w = s[i] - tau;
        unsigned mask = __ballot_sync(0xffffffffu, w > 0.0f);
        const int jb = (i >> 2) * 128 + (i & 3) * 32;
        while (mask) {
            int b = __ffs(mask) - 1;
            mask &= mask - 1;
            float wb = __shfl_sync(0xffffffffu, w, b);
            acc = fmaf(wb, __ldg(Vbh + (jb + b) * kDK + lane), acc);
        }
    }

    const int bb = bh >> 3;
    const int h  = bh & 7;
    out[(bb * kS + qi) * kDM + h * kDK + lane] = acc;
}

// ---------------------------------------------------------------------------
extern "C" void kernel_launch(void* const* d_in, const int* in_sizes, int n_in,
                              void* d_out, int out_size)
{
    const float* query = (const float*)d_in[0];
    const float* key   = (const float*)d_in[1];
    const float* value = (const float*)d_in[2];
    const float* Wq    = (const float*)d_in[3];
    const float* bq    = (const float*)d_in[4];
    const float* Wk    = (const float*)d_in[5];
    const float* bk    = (const float*)d_in[6];
    const float* Wv    = (const float*)d_in[7];
    const float* bv    = (const float*)d_in[8];
    float* out = (float*)d_out;

    dim3 pgrid(kDM / 64, kNRow / 128, 3);      // (4, 32, 3)
    proj_kernel<<<pgrid, 256>>>(query, key, value, Wq, bq, Wk, bk, Wv, bv);

    dim3 agrid(kS / 8, kB * kH);               // (256, 16)
    attn_kernel<<<agrid, 256>>>(out);

    (void)in_sizes; (void)n_in; (void)out_size;
}

// round 3
// speedup vs baseline: 1.0920x; 1.0920x over previous
#include <cuda_runtime.h>

namespace {
constexpr int kB  = 2;
constexpr int kH  = 8;
constexpr int kS  = 2048;
constexpr int kDK = 32;
constexpr int kDM = 256;
constexpr int kNRow = kB * kS;           // 4096
constexpr float kScale = 0.17677669529663687f;  // 1/sqrt(32)
}

// Scratch: projected Q/K/V in [b,h,s,d] layout (4 MB each).
__device__ float g_q[kB * kH * kS * kDK];
__device__ float g_k[kB * kH * kS * kDK];
__device__ float g_v[kB * kH * kS * kDK];

// ---------------------------------------------------------------------------
// Projection GEMM: out = X @ W^T + bias, written transposed to [b,h,s,d].
// Tile 128x64, 256 threads, 8x4 microtile, BK=16.   (unchanged — ~28us)
// ---------------------------------------------------------------------------
__global__ __launch_bounds__(256)
void proj_kernel(const float* __restrict__ xq, const float* __restrict__ xk,
                 const float* __restrict__ xv,
                 const float* __restrict__ wq, const float* __restrict__ bq,
                 const float* __restrict__ wk, const float* __restrict__ bk,
                 const float* __restrict__ wv, const float* __restrict__ bv)
{
    constexpr int PBM = 128, PBN = 64, PBK = 16;
    __shared__ float As[PBK][PBM];
    __shared__ float Bs[PBK][PBN];

    const int z = blockIdx.z;
    const float* __restrict__ X    = (z == 0) ? xq : (z == 1) ? xk : xv;
    const float* __restrict__ W    = (z == 0) ? wq : (z == 1) ? wk : wv;
    const float* __restrict__ bias = (z == 0) ? bq : (z == 1) ? bk : bv;
    float* __restrict__ out        = (z == 0) ? g_q : (z == 1) ? g_k : g_v;

    const int n0 = blockIdx.y * PBM;
    const int c0 = blockIdx.x * PBN;
    const int tid = threadIdx.x;
    const int tx = tid & 15;
    const int ty = tid >> 4;

    float acc[8][4];
    #pragma unroll
    for (int i = 0; i < 8; ++i)
        #pragma unroll
        for (int j = 0; j < 4; ++j) acc[i][j] = 0.0f;

    for (int k0 = 0; k0 < kDM; k0 += PBK) {
        #pragma unroll
        for (int r = 0; r < 2; ++r) {
            int f   = tid + r * 256;
            int row = f >> 2;
            int kk  = (f & 3) * 4;
            float4 v = *reinterpret_cast<const float4*>(X + (n0 + row) * kDM + k0 + kk);
            As[kk + 0][row] = v.x; As[kk + 1][row] = v.y;
            As[kk + 2][row] = v.z; As[kk + 3][row] = v.w;
        }
        {
            int n  = tid >> 2;
            int kk = (tid & 3) * 4;
            float4 v = *reinterpret_cast<const float4*>(W + (c0 + n) * kDM + k0 + kk);
            Bs[kk + 0][n] = v.x; Bs[kk + 1][n] = v.y;
            Bs[kk + 2][n] = v.z; Bs[kk + 3][n] = v.w;
        }
        __syncthreads();

        #pragma unroll
        for (int k = 0; k < PBK; ++k) {
            float4 a0 = *reinterpret_cast<const float4*>(&As[k][ty * 8]);
            float4 a1 = *reinterpret_cast<const float4*>(&As[k][ty * 8 + 4]);
            float4 bb = *reinterpret_cast<const float4*>(&Bs[k][tx * 4]);
            float a[8] = {a0.x, a0.y, a0.z, a0.w, a1.x, a1.y, a1.z, a1.w};
            float b[4] = {bb.x, bb.y, bb.z, bb.w};
            #pragma unroll
            for (int i = 0; i < 8; ++i)
                #pragma unroll
                for (int j = 0; j < 4; ++j)
                    acc[i][j] = fmaf(a[i], b[j], acc[i][j]);
        }
        __syncthreads();
    }

    #pragma unroll
    for (int i = 0; i < 8; ++i) {
        const int row = n0 + ty * 8 + i;
        const int bb  = row / kS;
        const int ss  = row % kS;
        #pragma unroll
        for (int j = 0; j < 4; ++j) {
            const int col = c0 + tx * 4 + j;
            const int h = col >> 5, d = col & 31;
            out[((bb * kH + h) * kS + ss) * kDK + d] = acc[i][j] + bias[col];
        }
    }
}

// ---------------------------------------------------------------------------
// Fused sparsemax attention: 1 warp = 1 query (2048 scores in 64 regs/lane),
// 8 warps/CTA share a K tile in shared. Register-trimmed for 2 CTAs/SM:
//  - outer tile loop NOT unrolled
//  - single live float4 in the score inner loop, 2 FMA chains
//  - __launch_bounds__(256, 2) caps regs at 128 (s[64]+q[32]=96 floor)
// ---------------------------------------------------------------------------
__global__ __launch_bounds__(256, 2)
void attn_kernel(float* __restrict__ out)
{
    __shared__ float4 Ks4[8 * 128];   // [d4][j], XOR-swizzled

    const int bh   = blockIdx.y;
    const int warp = threadIdx.x >> 5;
    const int lane = threadIdx.x & 31;
    const int qi   = blockIdx.x * 8 + warp;

    const float* __restrict__ Qrow = g_q + (bh * kS + qi) * kDK;
    const float* __restrict__ Kbh  = g_k + bh * kS * kDK;
    const float* __restrict__ Vbh  = g_v + bh * kS * kDK;

    // q row in registers (all lanes identical): 8 float4 = 32 regs
    float4 qv[8];
    #pragma unroll
    for (int d4 = 0; d4 < 8; ++d4)
        qv[d4] = __ldg(reinterpret_cast<const float4*>(Qrow) + d4);

    float s[64];   // score j = (i>>2)*128 + (i&3)*32 + lane

    #pragma unroll 1
    for (int t = 0; t < 16; ++t) {
        // Cooperative K tile load: 128 rows x 8 float4, transposed + swizzled
        #pragma unroll
        for (int r = 0; r < 4; ++r) {
            int f  = threadIdx.x + r * 256;
            int j  = f >> 3;
            int d4 = f & 7;
            Ks4[d4 * 128 + (j ^ d4)] =
                *reinterpret_cast<const float4*>(Kbh + (t * 128 + j) * kDK + d4 * 4);
        }
        __syncthreads();

        #pragma unroll
        for (int k = 0; k < 4; ++k) {
            const int j = k * 32 + lane;
            float a0 = 0.f, a1 = 0.f;   // 2 FMA chains, 1 live float4
            #pragma unroll
            for (int dd = 0; dd < 8; ++dd) {
                float4 kv = Ks4[dd * 128 + (j ^ dd)];
                a0 = fmaf(kv.x, (dd == 0 ? qv[0].x : dd == 1 ? qv[1].x : dd == 2 ? qv[2].x : dd == 3 ? qv[3].x : dd == 4 ? qv[4].x : dd == 5 ? qv[5].x : dd == 6 ? qv[6].x : qv[7].x), a0);
                a1 = fmaf(kv.y, (dd == 0 ? qv[0].y : dd == 1 ? qv[1].y : dd == 2 ? qv[2].y : dd == 3 ? qv[3].y : dd == 4 ? qv[4].y : dd == 5 ? qv[5].y : dd == 6 ? qv[6].y : qv[7].y), a1);
                a0 = fmaf(kv.z, (dd == 0 ? qv[0].z : dd == 1 ? qv[1].z : dd == 2 ? qv[2].z : dd == 3 ? qv[3].z : dd == 4 ? qv[4].z : dd == 5 ? qv[5].z : dd == 6 ? qv[6].z : qv[7].z), a0);
                a1 = fmaf(kv.w, (dd == 0 ? qv[0].w : dd == 1 ? qv[1].w : dd == 2 ? qv[2].w : dd == 3 ? qv[3].w : dd == 4 ? qv[4].w : dd == 5 ? qv[5].w : dd == 6 ? qv[6].w : qv[7].w), a1);
            }
            s[t * 4 + k] = (a0 + a1) * kScale;
        }
        __syncthreads();
    }

    // Row max over all 2048 scores
    float m = -3.4e38f;
    #pragma unroll
    for (int i = 0; i < 64; ++i) m = fmaxf(m, s[i]);
    #pragma unroll
    for (int o = 16; o; o >>= 1)
        m = fmaxf(m, __shfl_xor_sync(0xffffffffu, m, o));

    // Michelot fixpoint: tau monotone non-decreasing, support strictly
    // shrinking -> exact sparsemax tau at termination.
    float tau = m - 1.0f;
    int prev = -1;
    for (int it = 0; it < 4096; ++it) {
        float sum = 0.0f;
        int cnt = 0;
        #pragma unroll
        for (int i = 0; i < 64; ++i) {
            if (s[i] > tau) { sum += s[i]; ++cnt; }
        }
        #pragma unroll
        for (int o = 16; o; o >>= 1) {
            sum += __shfl_xor_sync(0xffffffffu, sum, o);
            cnt += __shfl_xor_sync(0xffffffffu, cnt, o);
        }
        if (cnt == prev || cnt == 0) break;
        tau = (sum - 1.0f) / (float)cnt;
        prev = cnt;
    }

    // Sparse AV: lane owns output dim d = lane; iterate nonzero weights only.
    float acc = 0.0f;
    #pragma unroll 1
    for (int i = 0; i < 64; ++i) {
        float w = s[i] - tau;
        unsigned mask = __ballot_sync(0xffffffffu, w > 0.0f);
        const float* __restrict__ Vb = Vbh + ((i >> 2) * 128 + (i & 3) * 32) * kDK + lane;
        while (mask) {
            int b = __ffs(mask) - 1;
            mask &= mask - 1;
            float wb = __shfl_sync(0xffffffffu, w, b);
            acc = fmaf(wb, __ldg(Vb + b * kDK), acc);
        }
    }

    const int bb = bh >> 3;
    const int h  = bh & 7;
    out[(bb * kS + qi) * kDM + h * kDK + lane] = acc;
}

// ---------------------------------------------------------------------------
extern "C" void kernel_launch(void* const* d_in, const int* in_sizes, int n_in,
                              void* d_out, int out_size)
{
    const float* query = (const float*)d_in[0];
    const float* key   = (const float*)d_in[1];
    const float* value = (const float*)d_in[2];
    const float* Wq    = (const float*)d_in[3];
    const float* bq    = (const float*)d_in[4];
    const float* Wk    = (const float*)d_in[5];
    const float* bk    = (const float*)d_in[6];
    const float* Wv    = (const float*)d_in[7];
    const float* bv    = (const float*)d_in[8];
    float* out = (float*)d_out;

    dim3 pgrid(kDM / 64, kNRow / 128, 3);      // (4, 32, 3)
    proj_kernel<<<pgrid, 256>>>(query, key, value, Wq, bq, Wk, bk, Wv, bv);

    dim3 agrid(kS / 8, kB * kH);               // (256, 16)
    attn_kernel<<<agrid, 256>>>(out);

    (void)in_sizes; (void)n_in; (void)out_size;
}

// round 4
// speedup vs baseline: 1.1457x; 1.0492x over previous
#include <cuda_runtime.h>

namespace {
constexpr int kB  = 2;
constexpr int kH  = 8;
constexpr int kS  = 2048;
constexpr int kDK = 32;
constexpr int kDM = 256;
constexpr int kNRow = kB * kS;           // 4096
constexpr float kScale = 0.17677669529663687f;  // 1/sqrt(32)
}

// Scratch: projected Q/K/V in [b,h,s,d] layout (4 MB each).
__device__ float g_q[kB * kH * kS * kDK];
__device__ float g_k[kB * kH * kS * kDK];
__device__ float g_v[kB * kH * kS * kDK];

// ---------------------------------------------------------------------------
// Projection GEMM: out = X @ W^T + bias, written transposed to [b,h,s,d].
// Tile 128x64, 256 threads, 8x4 microtile, BK=16.  (unchanged)
// ---------------------------------------------------------------------------
__global__ __launch_bounds__(256)
void proj_kernel(const float* __restrict__ xq, const float* __restrict__ xk,
                 const float* __restrict__ xv,
                 const float* __restrict__ wq, const float* __restrict__ bq,
                 const float* __restrict__ wk, const float* __restrict__ bk,
                 const float* __restrict__ wv, const float* __restrict__ bv)
{
    constexpr int PBM = 128, PBN = 64, PBK = 16;
    __shared__ float As[PBK][PBM];
    __shared__ float Bs[PBK][PBN];

    const int z = blockIdx.z;
    const float* __restrict__ X    = (z == 0) ? xq : (z == 1) ? xk : xv;
    const float* __restrict__ W    = (z == 0) ? wq : (z == 1) ? wk : wv;
    const float* __restrict__ bias = (z == 0) ? bq : (z == 1) ? bk : bv;
    float* __restrict__ out        = (z == 0) ? g_q : (z == 1) ? g_k : g_v;

    const int n0 = blockIdx.y * PBM;
    const int c0 = blockIdx.x * PBN;
    const int tid = threadIdx.x;
    const int tx = tid & 15;
    const int ty = tid >> 4;

    float acc[8][4];
    #pragma unroll
    for (int i = 0; i < 8; ++i)
        #pragma unroll
        for (int j = 0; j < 4; ++j) acc[i][j] = 0.0f;

    for (int k0 = 0; k0 < kDM; k0 += PBK) {
        #pragma unroll
        for (int r = 0; r < 2; ++r) {
            int f   = tid + r * 256;
            int row = f >> 2;
            int kk  = (f & 3) * 4;
            float4 v = *reinterpret_cast<const float4*>(X + (n0 + row) * kDM + k0 + kk);
            As[kk + 0][row] = v.x; As[kk + 1][row] = v.y;
            As[kk + 2][row] = v.z; As[kk + 3][row] = v.w;
        }
        {
            int n  = tid >> 2;
            int kk = (tid & 3) * 4;
            float4 v = *reinterpret_cast<const float4*>(W + (c0 + n) * kDM + k0 + kk);
            Bs[kk + 0][n] = v.x; Bs[kk + 1][n] = v.y;
            Bs[kk + 2][n] = v.z; Bs[kk + 3][n] = v.w;
        }
        __syncthreads();

        #pragma unroll
        for (int k = 0; k < PBK; ++k) {
            float4 a0 = *reinterpret_cast<const float4*>(&As[k][ty * 8]);
            float4 a1 = *reinterpret_cast<const float4*>(&As[k][ty * 8 + 4]);
            float4 bb = *reinterpret_cast<const float4*>(&Bs[k][tx * 4]);
            float a[8] = {a0.x, a0.y, a0.z, a0.w, a1.x, a1.y, a1.z, a1.w};
            float b[4] = {bb.x, bb.y, bb.z, bb.w};
            #pragma unroll
            for (int i = 0; i < 8; ++i)
                #pragma unroll
                for (int j = 0; j < 4; ++j)
                    acc[i][j] = fmaf(a[i], b[j], acc[i][j]);
        }
        __syncthreads();
    }

    #pragma unroll
    for (int i = 0; i < 8; ++i) {
        const int row = n0 + ty * 8 + i;
        const int bb  = row / kS;
        const int ss  = row % kS;
        #pragma unroll
        for (int j = 0; j < 4; ++j) {
            const int col = c0 + tx * 4 + j;
            const int h = col >> 5, d = col & 31;
            out[((bb * kH + h) * kS + ss) * kDK + d] = acc[i][j] + bias[col];
        }
    }
}

// ---------------------------------------------------------------------------
// Fused sparsemax attention, 2 queries per warp:
//  - each K float4 LDS feeds 8 FMAs (2 queries) -> smem phases/score halved
//  - q vectors live in shared, read via broadcast LDS (1 phase each)
//  - scores: sA[64] + sB[64] in registers (~170 regs, 1 CTA/SM, no spill)
//  - Michelot fixpoint tau, ballot/shfl sparse AV per query
// ---------------------------------------------------------------------------
__global__ __launch_bounds__(256, 1)
void attn_kernel(float* __restrict__ out)
{
    __shared__ float4 Ks4[8 * 128];    // [d4][j], XOR-swizzled
    __shared__ float4 Qs4[16 * 8];     // 16 queries x 8 float4

    const int bh   = blockIdx.y;
    const int warp = threadIdx.x >> 5;
    const int lane = threadIdx.x & 31;
    const int tid  = threadIdx.x;

    const int qA = blockIdx.x * 16 + warp * 2;      // this warp's queries
    const int qB = qA + 1;

    const float* __restrict__ Kbh = g_k + bh * kS * kDK;
    const float* __restrict__ Vbh = g_v + bh * kS * kDK;

    // Stage the CTA's 16 q rows into shared (128 float4)
    if (tid < 128) {
        const int qq = tid >> 3, d4 = tid & 7;
        Qs4[tid] = *reinterpret_cast<const float4*>(
            g_q + (bh * kS + blockIdx.x * 16 + qq) * kDK + d4 * 4);
    }

    float sA[64], sB[64];   // score j = (i>>2)*128 + (i&3)*32 + lane

    #pragma unroll 1
    for (int t = 0; t < 16; ++t) {
        __syncthreads();
        // Cooperative K tile load: 128 rows x 8 float4, transposed + swizzled
        #pragma unroll
        for (int r = 0; r < 4; ++r) {
            int f  = tid + r * 256;
            int j  = f >> 3;
            int d4 = f & 7;
            Ks4[d4 * 128 + (j ^ d4)] =
                *reinterpret_cast<const float4*>(Kbh + (t * 128 + j) * kDK + d4 * 4);
        }
        __syncthreads();

        float aA[4] = {0.f, 0.f, 0.f, 0.f};
        float aB[4] = {0.f, 0.f, 0.f, 0.f};
        #pragma unroll
        for (int dd = 0; dd < 8; ++dd) {
            const float4 qa = Qs4[(warp * 2 + 0) * 8 + dd];   // broadcast LDS
            const float4 qb = Qs4[(warp * 2 + 1) * 8 + dd];   // broadcast LDS
            #pragma unroll
            for (int k = 0; k < 4; ++k) {
                const float4 kv = Ks4[dd * 128 + ((k * 32 + lane) ^ dd)];
                aA[k] = fmaf(kv.x, qa.x, aA[k]);
                aA[k] = fmaf(kv.y, qa.y, aA[k]);
                aA[k] = fmaf(kv.z, qa.z, aA[k]);
                aA[k] = fmaf(kv.w, qa.w, aA[k]);
                aB[k] = fmaf(kv.x, qb.x, aB[k]);
                aB[k] = fmaf(kv.y, qb.y, aB[k]);
                aB[k] = fmaf(kv.z, qb.z, aB[k]);
                aB[k] = fmaf(kv.w, qb.w, aB[k]);
            }
        }
        #pragma unroll
        for (int k = 0; k < 4; ++k) {
            sA[t * 4 + k] = aA[k] * kScale;
            sB[t * 4 + k] = aB[k] * kScale;
        }
    }

    // Row max (both queries together)
    float mA = -3.4e38f, mB = -3.4e38f;
    #pragma unroll
    for (int i = 0; i < 64; ++i) { mA = fmaxf(mA, sA[i]); mB = fmaxf(mB, sB[i]); }
    #pragma unroll
    for (int o = 16; o; o >>= 1) {
        mA = fmaxf(mA, __shfl_xor_sync(0xffffffffu, mA, o));
        mB = fmaxf(mB, __shfl_xor_sync(0xffffffffu, mB, o));
    }

    // Michelot fixpoint (exact sparsemax tau), both queries in one loop
    float tauA = mA - 1.0f, tauB = mB - 1.0f;
    int prevA = -1, prevB = -1;
    bool doneA = false, doneB = false;
    for (int it = 0; it < 4096; ++it) {
        float sumA = 0.f, sumB = 0.f;
        int cntA = 0, cntB = 0;
        #pragma unroll
        for (int i = 0; i < 64; ++i) {
            if (sA[i] > tauA) { sumA += sA[i]; ++cntA; }
            if (sB[i] > tauB) { sumB += sB[i]; ++cntB; }
        }
        #pragma unroll
        for (int o = 16; o; o >>= 1) {
            sumA += __shfl_xor_sync(0xffffffffu, sumA, o);
            cntA += __shfl_xor_sync(0xffffffffu, cntA, o);
            sumB += __shfl_xor_sync(0xffffffffu, sumB, o);
            cntB += __shfl_xor_sync(0xffffffffu, cntB, o);
        }
        if (!doneA) {
            if (cntA == prevA || cntA == 0) doneA = true;
            else { tauA = (sumA - 1.0f) / (float)cntA; prevA = cntA; }
        }
        if (!doneB) {
            if (cntB == prevB || cntB == 0) doneB = true;
            else { tauB = (sumB - 1.0f) / (float)cntB; prevB = cntB; }
        }
        if (doneA && doneB) break;
    }

    // Sparse AV: lane owns output dim d = lane; iterate nonzero weights only.
    float accA = 0.0f, accB = 0.0f;
    #pragma unroll 1
    for (int i = 0; i < 64; ++i) {
        const float wA = sA[i] - tauA;
        const float wB = sB[i] - tauB;
        unsigned maskA = __ballot_sync(0xffffffffu, wA > 0.0f);
        unsigned maskB = __ballot_sync(0xffffffffu, wB > 0.0f);
        const float* __restrict__ Vb =
            Vbh + ((i >> 2) * 128 + (i & 3) * 32) * kDK + lane;
        while (maskA) {
            int b = __ffs(maskA) - 1;
            maskA &= maskA - 1;
            float wb = __shfl_sync(0xffffffffu, wA, b);
            accA = fmaf(wb, __ldg(Vb + b * kDK), accA);
        }
        while (maskB) {
            int b = __ffs(maskB) - 1;
            maskB &= maskB - 1;
            float wb = __shfl_sync(0xffffffffu, wB, b);
            accB = fmaf(wb, __ldg(Vb + b * kDK), accB);
        }
    }

    const int bb = bh >> 3;
    const int h  = bh & 7;
    out[(bb * kS + qA) * kDM + h * kDK + lane] = accA;
    out[(bb * kS + qB) * kDM + h * kDK + lane] = accB;
}

// ---------------------------------------------------------------------------
extern "C" void kernel_launch(void* const* d_in, const int* in_sizes, int n_in,
                              void* d_out, int out_size)
{
    const float* query = (const float*)d_in[0];
    const float* key   = (const float*)d_in[1];
    const float* value = (const float*)d_in[2];
    const float* Wq    = (const float*)d_in[3];
    const float* bq    = (const float*)d_in[4];
    const float* Wk    = (const float*)d_in[5];
    const float* bk    = (const float*)d_in[6];
    const float* Wv    = (const float*)d_in[7];
    const float* bv    = (const float*)d_in[8];
    float* out = (float*)d_out;

    dim3 pgrid(kDM / 64, kNRow / 128, 3);      // (4, 32, 3)
    proj_kernel<<<pgrid, 256>>>(query, key, value, Wq, bq, Wk, bk, Wv, bv);

    dim3 agrid(kS / 16, kB * kH);              // (128, 16)
    attn_kernel<<<agrid, 256>>>(out);

    (void)in_sizes; (void)n_in; (void)out_size;
}

// round 5
// speedup vs baseline: 1.1872x; 1.0362x over previous
#include <cuda_runtime.h>

namespace {
constexpr int kB  = 2;
constexpr int kH  = 8;
constexpr int kS  = 2048;
constexpr int kDK = 32;
constexpr int kDM = 256;
constexpr int kNRow = kB * kS;           // 4096
constexpr float kScale = 0.17677669529663687f;  // 1/sqrt(32)
constexpr int kQPerCta = 24;             // 12 warps x 2 queries
}

// Scratch: projected Q/K/V in [b,h,s,d] layout (4 MB each).
__device__ float g_q[kB * kH * kS * kDK];
__device__ float g_k[kB * kH * kS * kDK];
__device__ float g_v[kB * kH * kS * kDK];

// ---------------------------------------------------------------------------
// Projection GEMM: out = X @ W^T + bias, written transposed to [b,h,s,d].
// Tile 128x64, 256 threads, 8x4 microtile, BK=16.  (unchanged)
// ---------------------------------------------------------------------------
__global__ __launch_bounds__(256)
void proj_kernel(const float* __restrict__ xq, const float* __restrict__ xk,
                 const float* __restrict__ xv,
                 const float* __restrict__ wq, const float* __restrict__ bq,
                 const float* __restrict__ wk, const float* __restrict__ bk,
                 const float* __restrict__ wv, const float* __restrict__ bv)
{
    constexpr int PBM = 128, PBN = 64, PBK = 16;
    __shared__ float As[PBK][PBM];
    __shared__ float Bs[PBK][PBN];

    const int z = blockIdx.z;
    const float* __restrict__ X    = (z == 0) ? xq : (z == 1) ? xk : xv;
    const float* __restrict__ W    = (z == 0) ? wq : (z == 1) ? wk : wv;
    const float* __restrict__ bias = (z == 0) ? bq : (z == 1) ? bk : bv;
    float* __restrict__ out        = (z == 0) ? g_q : (z == 1) ? g_k : g_v;

    const int n0 = blockIdx.y * PBM;
    const int c0 = blockIdx.x * PBN;
    const int tid = threadIdx.x;
    const int tx = tid & 15;
    const int ty = tid >> 4;

    float acc[8][4];
    #pragma unroll
    for (int i = 0; i < 8; ++i)
        #pragma unroll
        for (int j = 0; j < 4; ++j) acc[i][j] = 0.0f;

    for (int k0 = 0; k0 < kDM; k0 += PBK) {
        #pragma unroll
        for (int r = 0; r < 2; ++r) {
            int f   = tid + r * 256;
            int row = f >> 2;
            int kk  = (f & 3) * 4;
            float4 v = *reinterpret_cast<const float4*>(X + (n0 + row) * kDM + k0 + kk);
            As[kk + 0][row] = v.x; As[kk + 1][row] = v.y;
            As[kk + 2][row] = v.z; As[kk + 3][row] = v.w;
        }
        {
            int n  = tid >> 2;
            int kk = (tid & 3) * 4;
            float4 v = *reinterpret_cast<const float4*>(W + (c0 + n) * kDM + k0 + kk);
            Bs[kk + 0][n] = v.x; Bs[kk + 1][n] = v.y;
            Bs[kk + 2][n] = v.z; Bs[kk + 3][n] = v.w;
        }
        __syncthreads();

        #pragma unroll
        for (int k = 0; k < PBK; ++k) {
            float4 a0 = *reinterpret_cast<const float4*>(&As[k][ty * 8]);
            float4 a1 = *reinterpret_cast<const float4*>(&As[k][ty * 8 + 4]);
            float4 bb = *reinterpret_cast<const float4*>(&Bs[k][tx * 4]);
            float a[8] = {a0.x, a0.y, a0.z, a0.w, a1.x, a1.y, a1.z, a1.w};
            float b[4] = {bb.x, bb.y, bb.z, bb.w};
            #pragma unroll
            for (int i = 0; i < 8; ++i)
                #pragma unroll
                for (int j = 0; j < 4; ++j)
                    acc[i][j] = fmaf(a[i], b[j], acc[i][j]);
        }
        __syncthreads();
    }

    #pragma unroll
    for (int i = 0; i < 8; ++i) {
        const int row = n0 + ty * 8 + i;
        const int bb  = row / kS;
        const int ss  = row % kS;
        #pragma unroll
        for (int j = 0; j < 4; ++j) {
            const int col = c0 + tx * 4 + j;
            const int h = col >> 5, d = col & 31;
            out[((bb * kH + h) * kS + ss) * kDK + d] = acc[i][j] + bias[col];
        }
    }
}

// ---------------------------------------------------------------------------
// Fused sparsemax attention, 2 queries per warp, 12 warps (384 thr) per CTA:
//  - each K float4 LDS feeds 8 FMAs (2 queries) -> low crossbar traffic
//  - q vectors in shared, broadcast LDS
//  - 162 regs < 170 cap (64K/384) -> 12 resident warps/SM (was 8)
//  - tail CTA clamps query pairs; redundant warps write identical values
// ---------------------------------------------------------------------------
__global__ __launch_bounds__(384, 1)
void attn_kernel(float* __restrict__ out)
{
    __shared__ float4 Ks4[8 * 128];        // [d4][j], XOR-swizzled
    __shared__ float4 Qs4[kQPerCta * 8];   // 24 queries x 8 float4

    const int bh   = blockIdx.y;
    const int warp = threadIdx.x >> 5;
    const int lane = threadIdx.x & 31;
    const int tid  = threadIdx.x;

    const int q0 = blockIdx.x * kQPerCta;
    int qA = q0 + warp * 2;
    if (qA > kS - 2) qA = kS - 2;          // tail clamp (consistent with staging)
    const int qB = qA + 1;

    const float* __restrict__ Kbh = g_k + bh * kS * kDK;
    const float* __restrict__ Vbh = g_v + bh * kS * kDK;

    // Stage the CTA's 24 q rows into shared (192 float4), pair-clamped
    if (tid < kQPerCta * 8) {
        const int ss = tid >> 3, d4 = tid & 7;
        int qr = q0 + (ss & ~1);
        if (qr > kS - 2) qr = kS - 2;
        qr += (ss & 1);
        Qs4[tid] = *reinterpret_cast<const float4*>(
            g_q + (bh * kS + qr) * kDK + d4 * 4);
    }

    float sA[64], sB[64];   // score j = (i>>2)*128 + (i&3)*32 + lane

    #pragma unroll 1
    for (int t = 0; t < 16; ++t) {
        __syncthreads();
        // Cooperative K tile load: 1024 float4, 384 threads
        #pragma unroll
        for (int r = 0; r < 3; ++r) {
            int f = tid + r * 384;
            if (f < 1024) {
                int j  = f >> 3;
                int d4 = f & 7;
                Ks4[d4 * 128 + (j ^ d4)] =
                    *reinterpret_cast<const float4*>(Kbh + (t * 128 + j) * kDK + d4 * 4);
            }
        }
        __syncthreads();

        float aA[4] = {0.f, 0.f, 0.f, 0.f};
        float aB[4] = {0.f, 0.f, 0.f, 0.f};
        #pragma unroll
        for (int dd = 0; dd < 8; ++dd) {
            const float4 qa = Qs4[(warp * 2 + 0) * 8 + dd];   // broadcast LDS
            const float4 qb = Qs4[(warp * 2 + 1) * 8 + dd];   // broadcast LDS
            #pragma unroll
            for (int k = 0; k < 4; ++k) {
                const float4 kv = Ks4[dd * 128 + ((k * 32 + lane) ^ dd)];
                aA[k] = fmaf(kv.x, qa.x, aA[k]);
                aA[k] = fmaf(kv.y, qa.y, aA[k]);
                aA[k] = fmaf(kv.z, qa.z, aA[k]);
                aA[k] = fmaf(kv.w, qa.w, aA[k]);
                aB[k] = fmaf(kv.x, qb.x, aB[k]);
                aB[k] = fmaf(kv.y, qb.y, aB[k]);
                aB[k] = fmaf(kv.z, qb.z, aB[k]);
                aB[k] = fmaf(kv.w, qb.w, aB[k]);
            }
        }
        #pragma unroll
        for (int k = 0; k < 4; ++k) {
            sA[t * 4 + k] = aA[k] * kScale;
            sB[t * 4 + k] = aB[k] * kScale;
        }
    }

    // Row max (both queries together)
    float mA = -3.4e38f, mB = -3.4e38f;
    #pragma unroll
    for (int i = 0; i < 64; ++i) { mA = fmaxf(mA, sA[i]); mB = fmaxf(mB, sB[i]); }
    #pragma unroll
    for (int o = 16; o; o >>= 1) {
        mA = fmaxf(mA, __shfl_xor_sync(0xffffffffu, mA, o));
        mB = fmaxf(mB, __shfl_xor_sync(0xffffffffu, mB, o));
    }

    // Michelot fixpoint (exact sparsemax tau), both queries in one loop
    float tauA = mA - 1.0f, tauB = mB - 1.0f;
    int prevA = -1, prevB = -1;
    bool doneA = false, doneB = false;
    for (int it = 0; it < 4096; ++it) {
        float sumA = 0.f, sumB = 0.f;
        int cntA = 0, cntB = 0;
        #pragma unroll
        for (int i = 0; i < 64; ++i) {
            if (sA[i] > tauA) { sumA += sA[i]; ++cntA; }
            if (sB[i] > tauB) { sumB += sB[i]; ++cntB; }
        }
        #pragma unroll
        for (int o = 16; o; o >>= 1) {
            sumA += __shfl_xor_sync(0xffffffffu, sumA, o);
            cntA += __shfl_xor_sync(0xffffffffu, cntA, o);
            sumB += __shfl_xor_sync(0xffffffffu, sumB, o);
            cntB += __shfl_xor_sync(0xffffffffu, cntB, o);
        }
        if (!doneA) {
            if (cntA == prevA || cntA == 0) doneA = true;
            else { tauA = (sumA - 1.0f) / (float)cntA; prevA = cntA; }
        }
        if (!doneB) {
            if (cntB == prevB || cntB == 0) doneB = true;
            else { tauB = (sumB - 1.0f) / (float)cntB; prevB = cntB; }
        }
        if (doneA && doneB) break;
    }

    // Sparse AV: lane owns output dim d = lane; iterate nonzero weights only.
    float accA = 0.0f, accB = 0.0f;
    #pragma unroll 1
    for (int i = 0; i < 64; ++i) {
        const float wA = sA[i] - tauA;
        const float wB = sB[i] - tauB;
        unsigned maskA = __ballot_sync(0xffffffffu, wA > 0.0f);
        unsigned maskB = __ballot_sync(0xffffffffu, wB > 0.0f);
        const float* __restrict__ Vb =
            Vbh + ((i >> 2) * 128 + (i & 3) * 32) * kDK + lane;
        while (maskA) {
            int b = __ffs(maskA) - 1;
            maskA &= maskA - 1;
            float wb = __shfl_sync(0xffffffffu, wA, b);
            accA = fmaf(wb, __ldg(Vb + b * kDK), accA);
        }
        while (maskB) {
            int b = __ffs(maskB) - 1;
            maskB &= maskB - 1;
            float wb = __shfl_sync(0xffffffffu, wB, b);
            accB = fmaf(wb, __ldg(Vb + b * kDK), accB);
        }
    }

    const int bb = bh >> 3;
    const int h  = bh & 7;
    out[(bb * kS + qA) * kDM + h * kDK + lane] = accA;
    out[(bb * kS + qB) * kDM + h * kDK + lane] = accB;
}

// ---------------------------------------------------------------------------
extern "C" void kernel_launch(void* const* d_in, const int* in_sizes, int n_in,
                              void* d_out, int out_size)
{
    const float* query = (const float*)d_in[0];
    const float* key   = (const float*)d_in[1];
    const float* value = (const float*)d_in[2];
    const float* Wq    = (const float*)d_in[3];
    const float* bq    = (const float*)d_in[4];
    const float* Wk    = (const float*)d_in[5];
    const float* bk    = (const float*)d_in[6];
    const float* Wv    = (const float*)d_in[7];
    const float* bv    = (const float*)d_in[8];
    float* out = (float*)d_out;

    dim3 pgrid(kDM / 64, kNRow / 128, 3);      // (4, 32, 3)
    proj_kernel<<<pgrid, 256>>>(query, key, value, Wq, bq, Wk, bk, Wv, bv);

    const int qblocks = (kS + kQPerCta - 1) / kQPerCta;   // 86
    dim3 agrid(qblocks, kB * kH);
    attn_kernel<<<agrid, 384>>>(out);

    (void)in_sizes; (void)n_in; (void)out_size;
}